// round 16
// baseline (speedup 1.0000x reference)
#include <cuda_runtime.h>

#define D       256
#define MMAX    5120
#define TOPK    32
#define INV_TAU 10.0f
#define PCOEF   0.25f      // BETA / (2*SIGMA^2)
#define PTHRESH 21.0f      // exact: >=32 cands with p<=1 dominate all p>21 (logit<-11)

#define QT 32              // queries per CTA tile
#define CT 128             // candidates per CTA tile
#define NBC (MMAX / CT)    // 40 candidate blocks
#define GRID1 (NBC * 4)    // 160 CTAs for fused kernel
#define CLSMAX  256
#define TCHUNK  12800      // bytes of `times` per CTA (mult of 16)

// smem byte layout (dynamic)
#define ASTR    264                 // A row stride in bf16 (528B; 4 banks mod 32)
#define KSTR    72                  // K row stride in bf16 (144B; 4 banks mod 32)
#define A_SEG   (QT * ASTR * 2)     // 16896 B per split
#define K_SEG   (CT * KSTR * 2)     // 18432 B per split
#define OFF_AHI 0
#define OFF_ALO (OFF_AHI + A_SEG)           // 16896
#define OFF_KB  (OFF_ALO + A_SEG)           // 33792 ; 4 segs: b0hi,b0lo,b1hi,b1lo
#define OFF_CIS (OFF_KB + 4 * K_SEG)        // 107520
#define DYN_SMEM 108032

__device__ int   g_count;
__device__ int   g_done;
__device__ int   g_bar;
__device__ int   g_ci[MMAX];
__device__ float g_cp[MMAX];
__device__ float g_qn[128 * D];
__device__ float g_logits[128 * MMAX];

__device__ __forceinline__ float neg_inf() { return __int_as_float(0xff800000); }

__device__ __forceinline__ void mbar_init(unsigned a, unsigned cnt) {
    asm volatile("mbarrier.init.shared.b64 [%0], %1;" :: "r"(a), "r"(cnt) : "memory");
}
__device__ __forceinline__ void mbar_expect_tx(unsigned a, unsigned tx) {
    asm volatile("mbarrier.arrive.expect_tx.shared.b64 _, [%0], %1;"
                 :: "r"(a), "r"(tx) : "memory");
}
__device__ __forceinline__ void bulk_g2s(unsigned dst, const void* src,
                                         unsigned bytes, unsigned mbar) {
    asm volatile("cp.async.bulk.shared::cta.global.mbarrier::complete_tx::bytes "
                 "[%0], [%1], %2, [%3];"
                 :: "r"(dst), "l"(src), "r"(bytes), "r"(mbar) : "memory");
}
__device__ __forceinline__ void mbar_wait(unsigned a, unsigned phase) {
    unsigned done;
    do {
        asm volatile("{\n\t.reg .pred p;\n\t"
                     "mbarrier.try_wait.parity.shared.b64 p, [%1], %2;\n\t"
                     "selp.b32 %0, 1, 0, p;\n\t}"
                     : "=r"(done) : "r"(a), "r"(phase) : "memory");
    } while (!done);
}

__device__ __forceinline__ void ldsm4(unsigned& r0, unsigned& r1,
                                      unsigned& r2, unsigned& r3, unsigned addr) {
    asm volatile("ldmatrix.sync.aligned.m8n8.x4.shared.b16 {%0,%1,%2,%3}, [%4];"
                 : "=r"(r0), "=r"(r1), "=r"(r2), "=r"(r3) : "r"(addr));
}
__device__ __forceinline__ void mma_bf16(float* d, const unsigned* a,
                                         unsigned b0, unsigned b1) {
    asm volatile("mma.sync.aligned.m16n8k16.row.col.f32.bf16.bf16.f32 "
                 "{%0,%1,%2,%3}, {%4,%5,%6,%7}, {%8,%9}, {%0,%1,%2,%3};"
                 : "+f"(d[0]), "+f"(d[1]), "+f"(d[2]), "+f"(d[3])
                 : "r"(a[0]), "r"(a[1]), "r"(a[2]), "r"(a[3]), "r"(b0), "r"(b1));
}
// pack two fp32 -> bf16x2 (f0 in low halfword = lower address)
__device__ __forceinline__ unsigned packbf16(float f0, float f1) {
    unsigned h;
    asm("cvt.rn.bf16x2.f32 %0, %2, %1;" : "=r"(h) : "f"(f0), "f"(f1));
    return h;
}
// split 32 fp32 (8 float4) into 16 hi + 16 lo bf16x2 words
__device__ __forceinline__ void split32(const float4* v, unsigned* hi, unsigned* lo) {
    #pragma unroll
    for (int i = 0; i < 8; i++) {
        unsigned h0 = packbf16(v[i].x, v[i].y);
        unsigned h1 = packbf16(v[i].z, v[i].w);
        float r0 = v[i].x - __uint_as_float(h0 << 16);
        float r1 = v[i].y - __uint_as_float(h0 & 0xffff0000u);
        float r2 = v[i].z - __uint_as_float(h1 << 16);
        float r3 = v[i].w - __uint_as_float(h1 & 0xffff0000u);
        hi[2*i]   = h0; hi[2*i+1] = h1;
        lo[2*i]   = packbf16(r0, r1);
        lo[2*i+1] = packbf16(r2, r3);
    }
}

// Fused: [TMA-bulk filter + qnorm] -> device-wide barrier -> [MMA logits].
// 160 CTAs x 256 threads, 108KB smem -> 2 CTAs/SM (216KB <= 228KB), all
// co-resident so the spin barrier cannot deadlock.
__global__ __launch_bounds__(256, 2) void fused_filter_logits_kernel(
        const float* __restrict__ Kbank,
        const float* __restrict__ query,
        const float* __restrict__ times,
        const float* __restrict__ qtime, int N) {
    extern __shared__ float smem[];
    char*    smc  = (char*)smem;
    unsigned sbase = (unsigned)__cvta_generic_to_shared(smem);
    int*     cis  = (int*)(smc + OFF_CIS);
    __shared__ float ws[8];
    __shared__ int   wbase[8];
    __shared__ int   sbasec;
    __shared__ alignas(8) unsigned long long s_mbar;

    int bid = blockIdx.x, t = threadIdx.x;
    int lane = t & 31, w = t >> 5;

    // ================= Phase A: TMA-bulk filter + qnorm =================
    {
        float* ks = (float*)(smc + OFF_KB);        // staging (overwritten in B)
        unsigned nbytes = (unsigned)N * 4u;
        unsigned off = (unsigned)bid * TCHUNK;
        unsigned size = 0;
        if (off < nbytes) size = min((unsigned)TCHUNK, nbytes - off);
        unsigned mb = (unsigned)__cvta_generic_to_shared(&s_mbar);

        if (t == 0) mbar_init(mb, 1);
        __syncthreads();
        if (t == 0 && size > 0) {
            mbar_expect_tx(mb, size);
            bulk_g2s(sbase + OFF_KB, (const char*)times + off, size, mb);
        }
        float qt = __ldg(qtime);

        if (bid < 128) {
            float v = query[bid * D + t];
            float s = v * v;
            #pragma unroll
            for (int o = 16; o > 0; o >>= 1) s += __shfl_xor_sync(0xffffffffu, s, o);
            if (lane == 0) ws[w] = s;
            __syncthreads();
            if (t < 32) {
                float x = (t < 8) ? ws[t] : 0.0f;
                #pragma unroll
                for (int o = 4; o > 0; o >>= 1) x += __shfl_xor_sync(0xffffffffu, x, o);
                if (t == 0) ws[0] = x;
            }
            __syncthreads();
            float norm = fmaxf(sqrtf(ws[0]), 1e-12f);
            g_qn[bid * D + t] = v / norm;
        }

        if (size > 0) mbar_wait(mb, 0);

        int nf4 = size >> 4;
        int gbase = bid * (TCHUNK / 4);
        int keep = 0;
        float ps[16]; int is[16];
        for (int j = t; j < nf4; j += 256) {
            float4 tv = *(const float4*)&ks[j * 4];
            float tt[4] = {tv.x, tv.y, tv.z, tv.w};
            int gi = gbase + j * 4;
            #pragma unroll
            for (int c = 0; c < 4; c++) {
                float dt = qt - tt[c];
                float p  = PCOEF * dt * dt;
                if (p <= PTHRESH) { ps[keep] = p; is[keep] = gi + c; keep++; }
            }
        }
        int x = keep;
        #pragma unroll
        for (int o = 1; o < 32; o <<= 1) {
            int y = __shfl_up_sync(0xffffffffu, x, o);
            if (lane >= o) x += y;
        }
        if (lane == 31) wbase[w] = x;
        __syncthreads();
        if (t < 32) {
            int wt = (t < 8) ? wbase[t] : 0;
            int xx = wt;
            #pragma unroll
            for (int o = 1; o < 8; o <<= 1) {
                int y = __shfl_up_sync(0xffffffffu, xx, o);
                if (t >= o) xx += y;
            }
            if (t < 8) wbase[t] = xx - wt;
            int btot = __shfl_sync(0xffffffffu, xx, 7);
            if (t == 0) sbasec = (btot > 0) ? atomicAdd(&g_count, btot) : 0;
        }
        __syncthreads();
        int myoff = sbasec + wbase[w] + x - keep;
        for (int k = 0; k < keep; k++) {
            int pos = myoff + k;
            if (pos < MMAX) { g_ci[pos] = is[k]; g_cp[pos] = ps[k]; }
        }
    }

    // ================= device-wide barrier =================
    __threadfence();
    __syncthreads();
    if (t == 0) {
        atomicAdd(&g_bar, 1);
        while (*(volatile int*)&g_bar < GRID1) { }
        __threadfence();
    }
    __syncthreads();

    // ================= Phase B: bf16-split MMA logits =================
    int cb = bid >> 2;
    int qb = bid & 3;
    int cbase = cb * CT;
    int qbase = qb * QT;

    int count  = min(g_count, MMAX);
    int cnt256 = (count + 255) & ~255;
    if (cbase >= cnt256) return;
    int nvalid = min(max(count - cbase, 0), CT);

    // warp tile: 16q x 32c
    int qr0 = (w & 1) * 16;
    int cc0 = (w >> 1) * 32;

    // stage candidate ids + convert q tile to split-bf16 smem
    if (t < CT) cis[t] = (t < nvalid) ? g_ci[cbase + t] : 0;
    {
        int row = t >> 3, cc = (t & 7) * 32;       // 32 rows x 8 chunks of 32
        float4 v[8];
        const float4* src = (const float4*)&g_qn[(qbase + row) * D + cc];
        #pragma unroll
        for (int i = 0; i < 8; i++) v[i] = src[i];
        unsigned hi[16], lo[16];
        split32(v, hi, lo);
        unsigned boff = (unsigned)(row * ASTR + cc) * 2;
        #pragma unroll
        for (int i = 0; i < 4; i++) {
            *(uint4*)(smc + OFF_AHI + boff + i * 16) =
                make_uint4(hi[4*i], hi[4*i+1], hi[4*i+2], hi[4*i+3]);
            *(uint4*)(smc + OFF_ALO + boff + i * 16) =
                make_uint4(lo[4*i], lo[4*i+1], lo[4*i+2], lo[4*i+3]);
        }
    }
    __syncthreads();

    int kr = t >> 1, kc = (t & 1) * 32;            // this thread's K row/cols
    const float* krow = Kbank + (size_t)cis[kr] * D;
    unsigned ksoff = (unsigned)(kr * KSTR + kc) * 2;

    float acc[4][4];
    #pragma unroll
    for (int i = 0; i < 4; i++)
        #pragma unroll
        for (int j = 0; j < 4; j++) acc[i][j] = 0.0f;

    float4 kreg[8];
    // prologue: chunk 0 -> regs -> split -> buf 0
    #pragma unroll
    for (int i = 0; i < 8; i++)
        kreg[i] = *(const float4*)&krow[0 * 64 + kc + i * 4];
    {
        unsigned hi[16], lo[16];
        split32(kreg, hi, lo);
        char* dh = smc + OFF_KB + 0 * 2 * K_SEG + ksoff;
        #pragma unroll
        for (int i = 0; i < 4; i++) {
            *(uint4*)(dh + i * 16) = make_uint4(hi[4*i], hi[4*i+1], hi[4*i+2], hi[4*i+3]);
            *(uint4*)(dh + K_SEG + i * 16) = make_uint4(lo[4*i], lo[4*i+1], lo[4*i+2], lo[4*i+3]);
        }
    }
    __syncthreads();

    // lane-fixed ldmatrix address components
    unsigned a_off = (unsigned)((qr0 + (lane & 15)) * ASTR + (lane >> 4) * 8) * 2;
    int brow0 = cc0 + (lane & 7) + ((lane >> 4) << 3);
    unsigned b_colpart = (unsigned)(((lane >> 3) & 1) * 8);

    #pragma unroll
    for (int s = 0; s < 4; s++) {
        if (s < 3) {                               // stage next chunk into regs
            #pragma unroll
            for (int i = 0; i < 8; i++)
                kreg[i] = *(const float4*)&krow[(s + 1) * 64 + kc + i * 4];
        }
        unsigned kb_hi = sbase + OFF_KB + (unsigned)(s & 1) * 2 * K_SEG;
        unsigned kb_lo = kb_hi + K_SEG;

        #pragma unroll
        for (int ks2 = 0; ks2 < 4; ks2++) {
            int kk = s * 4 + ks2;
            unsigned ah[4], al[4];
            unsigned aoff = a_off + (unsigned)(kk * 16) * 2;
            ldsm4(ah[0], ah[1], ah[2], ah[3], sbase + OFF_AHI + aoff);
            ldsm4(al[0], al[1], al[2], al[3], sbase + OFF_ALO + aoff);

            unsigned bcol = (unsigned)(ks2 * 16) + b_colpart;
            unsigned bo0 = (unsigned)(brow0 * KSTR) * 2 + bcol * 2;
            unsigned bo1 = bo0 + (unsigned)(16 * KSTR) * 2;
            unsigned bh[8], bl[8];
            ldsm4(bh[0], bh[1], bh[2], bh[3], kb_hi + bo0);
            ldsm4(bh[4], bh[5], bh[6], bh[7], kb_hi + bo1);
            ldsm4(bl[0], bl[1], bl[2], bl[3], kb_lo + bo0);
            ldsm4(bl[4], bl[5], bl[6], bl[7], kb_lo + bo1);

            #pragma unroll
            for (int nf = 0; nf < 4; nf++) {
                mma_bf16(acc[nf], ah, bh[nf*2], bh[nf*2+1]);
                mma_bf16(acc[nf], ah, bl[nf*2], bl[nf*2+1]);
                mma_bf16(acc[nf], al, bh[nf*2], bh[nf*2+1]);
            }
        }

        if (s < 3) {                               // split + store next chunk
            __syncthreads();
            unsigned hi[16], lo[16];
            split32(kreg, hi, lo);
            char* dh = smc + OFF_KB + (unsigned)((s + 1) & 1) * 2 * K_SEG + ksoff;
            #pragma unroll
            for (int i = 0; i < 4; i++) {
                *(uint4*)(dh + i * 16) = make_uint4(hi[4*i], hi[4*i+1], hi[4*i+2], hi[4*i+3]);
                *(uint4*)(dh + K_SEG + i * 16) = make_uint4(lo[4*i], lo[4*i+1], lo[4*i+2], lo[4*i+3]);
            }
            __syncthreads();
        }
    }

    // epilogue: scale, penalty, write (m16n8 D-fragment layout)
    int erow0 = qbase + qr0 + (lane >> 2);
    #pragma unroll
    for (int nf = 0; nf < 4; nf++) {
        int c0 = cbase + cc0 + nf * 8 + (lane & 3) * 2;
        #pragma unroll
        for (int h = 0; h < 2; h++) {              // h=0: rows, h=1: rows+8
            int r = erow0 + h * 8;
            #pragma unroll
            for (int e = 0; e < 2; e++) {          // col, col+1
                int c = c0 + e;
                float dot = acc[nf][h * 2 + e];
                float val = (c < count) ? fmaf(dot, INV_TAU, -g_cp[c]) : neg_inf();
                g_logits[r * MMAX + c] = val;
            }
        }
    }
}

// Exact top-32 per query (proven 27.10us version): fused load/transform/lvl-0
// hist, 11/11/10-bit radix, early exit to exact in-class rank, softmax, split
// V gather. Last-finishing block resets g_count/g_done/g_bar.
__global__ __launch_bounds__(1024) void topk_kernel(const float* __restrict__ Vbank,
                                                    float* __restrict__ out) {
    __shared__ unsigned su[MMAX];
    __shared__ int hist[2048];
    __shared__ int wtot[32];
    __shared__ unsigned clsu[CLSMAX];
    __shared__ int   clsj[CLSMAX];
    __shared__ unsigned selu[TOPK];
    __shared__ int   selj[TOPK];
    __shared__ float attn[TOPK];
    __shared__ int s_b, s_above, s_cls, s_ngt, s_ncls;

    int b = blockIdx.x, t = threadIdx.x;
    int lane = t & 31, w = t >> 5;
    int count = min(g_count, MMAX);
    int cnt256 = (count + 255) & ~255;
    int n4 = cnt256 >> 2;

    for (int i = t; i < 2048; i += 1024) hist[i] = 0;
    __syncthreads();

    for (int j4b = 0; j4b < n4; j4b += 1024) {
        int j4 = j4b + t;
        bool ok = j4 < n4;
        unsigned u[4];
        if (ok) {
            float4 v = *(const float4*)&g_logits[b * MMAX + j4 * 4];
            unsigned b0 = __float_as_uint(v.x), b1 = __float_as_uint(v.y);
            unsigned b2 = __float_as_uint(v.z), b3 = __float_as_uint(v.w);
            u[0] = (b0 & 0x80000000u) ? ~b0 : (b0 | 0x80000000u);
            u[1] = (b1 & 0x80000000u) ? ~b1 : (b1 | 0x80000000u);
            u[2] = (b2 & 0x80000000u) ? ~b2 : (b2 | 0x80000000u);
            u[3] = (b3 & 0x80000000u) ? ~b3 : (b3 | 0x80000000u);
            *(uint4*)&su[j4 * 4] = make_uint4(u[0], u[1], u[2], u[3]);
        }
        #pragma unroll
        for (int e = 0; e < 4; e++) {
            unsigned act = __ballot_sync(0xffffffffu, ok);
            if (ok) {
                unsigned bin = u[e] >> 21;
                unsigned peers = __match_any_sync(act, bin);
                if (lane == (__ffs(peers) - 1))
                    atomicAdd(&hist[bin], __popc(peers));
            }
        }
    }
    __syncthreads();

    const int shifts[3] = {21, 10, 0};
    const int nbits[3]  = {11, 11, 10};
    unsigned pmask = 0, pval = 0;
    int need = TOPK;

    for (int lvl = 0; lvl < 3; lvl++) {
        int shift = shifts[lvl];
        int nb = 1 << nbits[lvl];
        unsigned bmask = (unsigned)(nb - 1);
        int bpt = (nb > 1024) ? (nb >> 10) : 1;

        if (lvl > 0) {
            for (int i = t; i < nb; i += 1024) hist[i] = 0;
            __syncthreads();
            for (int jb = 0; jb < cnt256; jb += 1024) {
                int j = jb + t;
                unsigned u = (j < cnt256) ? su[j] : 0u;
                bool ok = (j < cnt256) && ((u & pmask) == pval);
                unsigned act = __ballot_sync(0xffffffffu, ok);
                if (ok) {
                    unsigned bin = (u >> shift) & bmask;
                    unsigned peers = __match_any_sync(act, bin);
                    if (lane == (__ffs(peers) - 1))
                        atomicAdd(&hist[bin], __popc(peers));
                }
            }
            __syncthreads();
        }

        int s = 0;
        int tb = t * bpt;
        #pragma unroll 2
        for (int i = 0; i < bpt; i++)
            if (tb + i < nb) s += hist[tb + i];
        int x = s;
        #pragma unroll
        for (int o = 1; o < 32; o <<= 1) {
            int y = __shfl_down_sync(0xffffffffu, x, o);
            if (lane + o < 32) x += y;
        }
        if (lane == 0) wtot[w] = x;
        __syncthreads();
        if (t < 32) {
            int ww = wtot[t];
            int xx = ww;
            #pragma unroll
            for (int o = 1; o < 32; o <<= 1) {
                int y = __shfl_down_sync(0xffffffffu, xx, o);
                if (t + o < 32) xx += y;
            }
            wtot[t] = xx - ww;
        }
        __syncthreads();
        int S = x + wtot[w];
        int Snext = S - s;

        if (S >= need && Snext < need) {
            int c = Snext;
            int bb = tb + bpt - 1;
            while (c + hist[bb] < need) { c += hist[bb]; bb--; }
            s_b = bb; s_above = c; s_cls = hist[bb];
        }
        __syncthreads();
        pval  |= ((unsigned)s_b) << shift;
        pmask |= bmask << shift;
        need  -= s_above;
        if (s_cls <= CLSMAX) break;
        __syncthreads();
    }

    if (t == 0) { s_ngt = 0; s_ncls = 0; }
    __syncthreads();
    for (int j = t; j < cnt256; j += 1024) {
        unsigned u = su[j];
        unsigned m = u & pmask;
        if (m > pval) {
            int p = atomicAdd(&s_ngt, 1);
            selu[p] = u; selj[p] = j;
        } else if (m == pval) {
            int p = atomicAdd(&s_ncls, 1);
            if (p < CLSMAX) { clsu[p] = u; clsj[p] = j; }
        }
    }
    __syncthreads();

    int ngt  = s_ngt;
    int clsN = min(s_ncls, CLSMAX);
    if (t < clsN) {
        unsigned ui = clsu[t]; int ji = clsj[t];
        int rank = 0;
        for (int j = 0; j < clsN; j++) {
            unsigned uj = clsu[j]; int jj = clsj[j];
            rank += (uj > ui || (uj == ui && jj < ji)) ? 1 : 0;
        }
        if (rank < need) { selu[ngt + rank] = ui; selj[ngt + rank] = ji; }
    }
    __syncthreads();

    if (t < 32) {
        unsigned u = selu[t];
        unsigned bits = (u & 0x80000000u) ? (u ^ 0x80000000u) : ~u;
        float v = __int_as_float(bits);
        float m = v;
        #pragma unroll
        for (int o = 16; o > 0; o >>= 1) m = fmaxf(m, __shfl_xor_sync(0xffffffffu, m, o));
        float e = expf(v - m);
        float sm = e;
        #pragma unroll
        for (int o = 16; o > 0; o >>= 1) sm += __shfl_xor_sync(0xffffffffu, sm, o);
        attn[t] = e / sm;
        selj[t] = g_ci[selj[t]];
    }
    __syncthreads();

    float* red = (float*)hist;
    int kg = t >> 8, d = t & 255;
    float part = 0.0f;
    #pragma unroll
    for (int k = 0; k < 8; k++) {
        int kk = kg * 8 + k;
        part = fmaf(attn[kk], Vbank[(size_t)selj[kk] * D + d], part);
    }
    red[kg * 256 + d] = part;
    __syncthreads();
    if (t < 256)
        out[b * D + t] = (red[t] + red[256 + t]) + (red[512 + t] + red[768 + t]);
    __syncthreads();

    if (t == 0) {
        int ticket = atomicAdd(&g_done, 1);
        if (ticket == (int)gridDim.x - 1) { g_done = 0; g_count = 0; g_bar = 0; }
    }
}

extern "C" void kernel_launch(void* const* d_in, const int* in_sizes, int n_in,
                              void* d_out, int out_size) {
    const float* query = (const float*)d_in[0];
    const float* Kbank = (const float*)d_in[1];
    const float* Vbank = (const float*)d_in[2];
    const float* times = (const float*)d_in[3];
    const float* qtime = (const float*)d_in[4];
    float* out = (float*)d_out;

    int N = in_sizes[3];        // 500000

    static int smem_set = 0;
    if (!smem_set) {
        cudaFuncSetAttribute(fused_filter_logits_kernel,
                             cudaFuncAttributeMaxDynamicSharedMemorySize, DYN_SMEM);
        smem_set = 1;
    }

    fused_filter_logits_kernel<<<GRID1, 256, DYN_SMEM>>>(
        Kbank, query, times, qtime, N);
    topk_kernel<<<128, 1024>>>(Vbank, out);
}